// round 3
// baseline (speedup 1.0000x reference)
#include <cuda_runtime.h>

#define TT 4096
#define BB 64
#define HH 512
#define GRID 128
#define NTH 256
#define KTOT 576        // 512 (h) + 64 (x)
#define WSTRIDE 585     // padded so 4 warp row-groups hit distinct banks
#define PSTR 68         // padded partial-row stride
#define HB (HH*BB)      // 32768 floats per h buffer

__device__ __align__(16) float g_hbuf[2*HB];
__device__ int g_flags[GRID];

__device__ __forceinline__ float sigf(float x){ return 1.f/(1.f+__expf(-x)); }
__device__ __forceinline__ float tanhf_fast(float x){
    float e = __expf(-2.f*fabsf(x));
    float r = (1.f-e)/(1.f+e);
    return copysignf(r, x);
}

__device__ __forceinline__ void cp16(unsigned dst, const void* src){
    asm volatile("cp.async.cg.shared.global [%0], [%1], 16;\n"::"r"(dst),"l"(src));
}
__device__ __forceinline__ void cp_commit(){ asm volatile("cp.async.commit_group;\n"::); }
#define CP_WAIT(N) asm volatile("cp.async.wait_group %0;\n"::"n"(N))

__global__ void __launch_bounds__(128,1) stn_init_kernel(){
    int i = blockIdx.x*blockDim.x + threadIdx.x;
    if (i < 2*HB) g_hbuf[i] = 0.f;
    if (i < GRID) g_flags[i] = 0;
}

// 16 FMAs per k; k strided by 4 across the 4 warp-groups.
#define GEMM_RANGE(K0,K1)                                                      \
    _Pragma("unroll 4")                                                        \
    for (int k = (K0) + wg; k < (K1); k += 4){                                 \
        const float4 h0 = *reinterpret_cast<const float4*>(sH + k*BB + b0);    \
        const float4 h1 = *reinterpret_cast<const float4*>(sH + k*BB + b0+4);  \
        const float w0 = w0p[k];                                               \
        const float w1 = w1p[k];                                               \
        acc[ 0]=fmaf(w0,h0.x,acc[ 0]); acc[ 1]=fmaf(w0,h0.y,acc[ 1]);          \
        acc[ 2]=fmaf(w0,h0.z,acc[ 2]); acc[ 3]=fmaf(w0,h0.w,acc[ 3]);          \
        acc[ 4]=fmaf(w0,h1.x,acc[ 4]); acc[ 5]=fmaf(w0,h1.y,acc[ 5]);          \
        acc[ 6]=fmaf(w0,h1.z,acc[ 6]); acc[ 7]=fmaf(w0,h1.w,acc[ 7]);          \
        acc[ 8]=fmaf(w1,h0.x,acc[ 8]); acc[ 9]=fmaf(w1,h0.y,acc[ 9]);          \
        acc[10]=fmaf(w1,h0.z,acc[10]); acc[11]=fmaf(w1,h0.w,acc[11]);          \
        acc[12]=fmaf(w1,h1.x,acc[12]); acc[13]=fmaf(w1,h1.y,acc[13]);          \
        acc[14]=fmaf(w1,h1.z,acc[14]); acc[15]=fmaf(w1,h1.w,acc[15]);          \
    }

__global__ void __launch_bounds__(NTH,1) stn_kernel(
    const float* __restrict__ x,      // [64,4096,64]
    const float* __restrict__ W_ih,   // [2048,64]
    const float* __restrict__ W_hh,   // [2048,512]
    const float* __restrict__ b_ih,   // [2048]
    const float* __restrict__ b_hh,   // [2048]
    float* __restrict__ out_states,   // [64,4096,512]
    float* __restrict__ out_final)    // [64,1024]
{
    extern __shared__ float smem[];
    float* sH = smem;                    // [576][64]
    float* sW = sH + KTOT*BB;            // [16][585]
    float* sP = sW + 16*WSTRIDE;         // [4][16][68] k-split partials
    float* sB = sP + 4*16*PSTR;          // [16]
    float* sC = sB + 16;                 // [4][64] cell state
    float* sO = sC + 4*BB;               // [4][64] h output staging

    const int tid = threadIdx.x;
    const int u0  = blockIdx.x * 4;      // this CTA's 4 hidden units

    // ---- load weights once: local row lr = gate*4 + j -> global row gate*512 + u0 + j
    for (int idx = tid; idx < 16*KTOT; idx += NTH){
        int lr = idx / KTOT, k = idx - lr*KTOT;
        int g = lr >> 2, j = lr & 3;
        int gr = g*HH + u0 + j;
        float w = (k < HH) ? W_hh[(size_t)gr*HH + k] : W_ih[gr*64 + (k - HH)];
        sW[lr*WSTRIDE + k] = w;
    }
    if (tid < 16){
        int g = tid >> 2, j = tid & 3;
        int gr = g*HH + u0 + j;
        sB[tid] = b_ih[gr] + b_hh[gr];
    }
    for (int idx = tid; idx < 4*BB; idx += NTH) sC[idx] = 0.f;
    __syncthreads();

    const unsigned sH_addr = (unsigned)__cvta_generic_to_shared(sH);
    const int wg = tid >> 6;             // k-split group 0..3
    const int wt = tid & 63;
    const int r0 = (wt >> 3) << 1;       // rows {r0, r0+1} of 16
    const int b0 = (wt & 7) << 3;        // batches [b0, b0+8)
    const float* w0p = sW + r0*WSTRIDE;
    const float* w1p = w0p + WSTRIDE;
    const int bx = tid >> 2, q = tid & 3;   // x staging assignment

    for (int t = 0; t < TT; ++t){
        const float* hsrc = g_hbuf + (size_t)(t & 1)*HB;

        // async copy of full h (4 chunks of 128 unit-rows) overlapped with compute
#pragma unroll
        for (int c = 0; c < 4; ++c){
#pragma unroll
            for (int i = 0; i < 8; ++i){
                int v = c*2048 + i*NTH + tid;   // float4 index
                cp16(sH_addr + v*16, hsrc + v*4);
            }
            cp_commit();
        }

        // x_t: each thread loads 16 floats of x and stages transposed into sH rows 512..575
        {
            const float* xp = x + ((size_t)bx*TT + t)*64 + q*16;
            float4 xr[4];
#pragma unroll
            for (int i = 0; i < 4; ++i) xr[i] = *reinterpret_cast<const float4*>(xp + i*4);
#pragma unroll
            for (int i = 0; i < 4; ++i){
                int kr = HH + q*16 + i*4;
                sH[(kr  )*BB + bx] = xr[i].x;
                sH[(kr+1)*BB + bx] = xr[i].y;
                sH[(kr+2)*BB + bx] = xr[i].z;
                sH[(kr+3)*BB + bx] = xr[i].w;
            }
        }

        float acc[16];
#pragma unroll
        for (int i = 0; i < 16; ++i) acc[i] = 0.f;

        CP_WAIT(3); __syncthreads();
        GEMM_RANGE(0, 128);
        CP_WAIT(2); __syncthreads();
        GEMM_RANGE(128, 256);
        CP_WAIT(1); __syncthreads();
        GEMM_RANGE(256, 384);
        CP_WAIT(0); __syncthreads();
        GEMM_RANGE(384, 512);
        GEMM_RANGE(512, 576);   // x rows staged before first sync above

        // write k-partials
        {
            float* p0 = sP + (wg*16 + r0)*PSTR + b0;
            float* p1 = sP + (wg*16 + r0 + 1)*PSTR + b0;
            *reinterpret_cast<float4*>(p0    ) = make_float4(acc[0],acc[1],acc[2],acc[3]);
            *reinterpret_cast<float4*>(p0 + 4) = make_float4(acc[4],acc[5],acc[6],acc[7]);
            *reinterpret_cast<float4*>(p1    ) = make_float4(acc[8],acc[9],acc[10],acc[11]);
            *reinterpret_cast<float4*>(p1 + 4) = make_float4(acc[12],acc[13],acc[14],acc[15]);
        }
        __syncthreads();

        // ---- epilogue: 256 threads, one (unit j, batch b) output each
        {
            const int j = tid >> 6, b = tid & 63;
            float gi = 0.f, gf = 0.f, gg = 0.f, go = 0.f;
#pragma unroll
            for (int p = 0; p < 4; ++p){
                gi += sP[(p*16 +      j)*PSTR + b];
                gf += sP[(p*16 +  4 + j)*PSTR + b];
                gg += sP[(p*16 +  8 + j)*PSTR + b];
                go += sP[(p*16 + 12 + j)*PSTR + b];
            }
            gi += sB[j]; gf += sB[4+j]; gg += sB[8+j]; go += sB[12+j];
            float iv = sigf(gi), fv = sigf(gf);
            float gv = tanhf_fast(gg), ov = sigf(go);
            float cold = sC[j*BB + b];
            float hold = sH[(u0+j)*BB + b];
            float cn = fv*cold + iv*gv;
            float hn = ov*tanhf_fast(cn);
            float h2 = 0.5f*(hold + hn);   // K = 0.5 Euler blend
            float c2 = 0.5f*(cold + cn);
            sC[j*BB + b] = c2;
            sO[j*BB + b] = h2;
            g_hbuf[(size_t)((t+1)&1)*HB + (u0+j)*BB + b] = h2;
        }
        __syncthreads();

        // coalesced 16B stores of the step output
        if (tid < BB){
            int b = tid;
            float4 hv4 = make_float4(sO[b], sO[BB+b], sO[2*BB+b], sO[3*BB+b]);
            *reinterpret_cast<float4*>(out_states + ((size_t)b*TT + t)*HH + u0) = hv4;
            if (t == TT-1){
                float4 cv4 = make_float4(sC[b], sC[BB+b], sC[2*BB+b], sC[3*BB+b]);
                *reinterpret_cast<float4*>(out_final + b*(2*HH) + u0) = hv4;
                *reinterpret_cast<float4*>(out_final + b*(2*HH) + HH + u0) = cv4;
            }
        }

        // ---- grid-wide step barrier (all 128 CTAs co-resident; flags monotonic)
        if (t != TT-1){
            if (tid == 0){
                asm volatile("st.release.gpu.global.u32 [%0], %1;\n"
                             :: "l"(&g_flags[blockIdx.x]), "r"((unsigned)(t+1)) : "memory");
            }
            if (tid < GRID){
                unsigned v;
                const int* fp = &g_flags[tid];
                do {
                    asm volatile("ld.acquire.gpu.global.u32 %0, [%1];\n"
                                 : "=r"(v) : "l"(fp) : "memory");
                } while (v < (unsigned)(t+1));
            }
            __syncthreads();
        }
    }
}

extern "C" void kernel_launch(void* const* d_in, const int* in_sizes, int n_in,
                              void* d_out, int out_size)
{
    const float* x    = (const float*)d_in[0];
    const float* W_ih = (const float*)d_in[1];
    const float* W_hh = (const float*)d_in[2];
    const float* b_ih = (const float*)d_in[3];
    const float* b_hh = (const float*)d_in[4];
    float* out        = (float*)d_out;
    float* out_final  = out + (size_t)BB*TT*HH;

    const int smem_bytes = (KTOT*BB + 16*WSTRIDE + 4*16*PSTR + 16 + 4*BB + 4*BB) * 4;
    cudaFuncSetAttribute(stn_kernel, cudaFuncAttributeMaxDynamicSharedMemorySize, smem_bytes);

    stn_init_kernel<<<(2*HB + 127)/128, 128>>>();
    stn_kernel<<<GRID, NTH, smem_bytes>>>(x, W_ih, W_hh, b_ih, b_hh, out, out_final);
}

// round 5
// speedup vs baseline: 1.0031x; 1.0031x over previous
#include <cuda_runtime.h>

#define TT 4096
#define BB 64
#define HH 512
#define GRID 128
#define NTH 256
#define KTOT 576        // 512 (h) + 64 (x)
#define WSTRIDE 585     // padded so 4 warp row-groups hit distinct banks
#define PSTR 68         // padded partial-row stride
#define HB (HH*BB)      // 32768 floats per h buffer

__device__ __align__(16) float g_hbuf[2*HB];
__device__ int g_flags[GRID];

__device__ __forceinline__ float sigf(float x){ return 1.f/(1.f+__expf(-x)); }
__device__ __forceinline__ float tanhf_fast(float x){
    float e = __expf(-2.f*fabsf(x));
    float r = (1.f-e)/(1.f+e);
    return copysignf(r, x);
}

__device__ __forceinline__ void cp16(unsigned dst, const void* src){
    asm volatile("cp.async.cg.shared.global [%0], [%1], 16;\n"::"r"(dst),"l"(src));
}
__device__ __forceinline__ void cp_commit(){ asm volatile("cp.async.commit_group;\n"::); }
#define CP_WAIT(N) asm volatile("cp.async.wait_group %0;\n"::"n"(N))

__global__ void __launch_bounds__(128,1) stn_init_kernel(){
    int i = blockIdx.x*blockDim.x + threadIdx.x;
    if (i < 2*HB) g_hbuf[i] = 0.f;
    if (i < GRID) g_flags[i] = 0;
}

// 16 FMAs per k; k strided by 4 across the 4 warp-groups.
#define GEMM_RANGE(K0,K1)                                                      \
    _Pragma("unroll 4")                                                        \
    for (int k = (K0) + wg; k < (K1); k += 4){                                 \
        const float4 h0 = *reinterpret_cast<const float4*>(sH + k*BB + b0);    \
        const float4 h1 = *reinterpret_cast<const float4*>(sH + k*BB + b0+4);  \
        const float w0 = w0p[k];                                               \
        const float w1 = w1p[k];                                               \
        acc[ 0]=fmaf(w0,h0.x,acc[ 0]); acc[ 1]=fmaf(w0,h0.y,acc[ 1]);          \
        acc[ 2]=fmaf(w0,h0.z,acc[ 2]); acc[ 3]=fmaf(w0,h0.w,acc[ 3]);          \
        acc[ 4]=fmaf(w0,h1.x,acc[ 4]); acc[ 5]=fmaf(w0,h1.y,acc[ 5]);          \
        acc[ 6]=fmaf(w0,h1.z,acc[ 6]); acc[ 7]=fmaf(w0,h1.w,acc[ 7]);          \
        acc[ 8]=fmaf(w1,h0.x,acc[ 8]); acc[ 9]=fmaf(w1,h0.y,acc[ 9]);          \
        acc[10]=fmaf(w1,h0.z,acc[10]); acc[11]=fmaf(w1,h0.w,acc[11]);          \
        acc[12]=fmaf(w1,h1.x,acc[12]); acc[13]=fmaf(w1,h1.y,acc[13]);          \
        acc[14]=fmaf(w1,h1.z,acc[14]); acc[15]=fmaf(w1,h1.w,acc[15]);          \
    }

__global__ void __launch_bounds__(NTH,1) stn_kernel(
    const float* __restrict__ x,      // [64,4096,64]
    const float* __restrict__ W_ih,   // [2048,64]
    const float* __restrict__ W_hh,   // [2048,512]
    const float* __restrict__ b_ih,   // [2048]
    const float* __restrict__ b_hh,   // [2048]
    float* __restrict__ out_states,   // [64,4096,512]
    float* __restrict__ out_final)    // [64,1024]
{
    extern __shared__ float smem[];
    float* sH = smem;                    // [576][64]
    float* sW = sH + KTOT*BB;            // [16][585]
    float* sP = sW + 16*WSTRIDE;         // [4][16][68] k-split partials
    float* sB = sP + 4*16*PSTR;          // [16]
    float* sC = sB + 16;                 // [4][64] cell state
    float* sO = sC + 4*BB;               // [4][64] h output staging

    const int tid = threadIdx.x;
    const int u0  = blockIdx.x * 4;      // this CTA's 4 hidden units

    // ---- load weights once: local row lr = gate*4 + j -> global row gate*512 + u0 + j
    for (int idx = tid; idx < 16*KTOT; idx += NTH){
        int lr = idx / KTOT, k = idx - lr*KTOT;
        int g = lr >> 2, j = lr & 3;
        int gr = g*HH + u0 + j;
        float w = (k < HH) ? W_hh[(size_t)gr*HH + k] : W_ih[gr*64 + (k - HH)];
        sW[lr*WSTRIDE + k] = w;
    }
    if (tid < 16){
        int g = tid >> 2, j = tid & 3;
        int gr = g*HH + u0 + j;
        sB[tid] = b_ih[gr] + b_hh[gr];
    }
    for (int idx = tid; idx < 4*BB; idx += NTH) sC[idx] = 0.f;
    __syncthreads();

    const unsigned sH_addr = (unsigned)__cvta_generic_to_shared(sH);
    const int wg = tid >> 6;             // k-split group 0..3
    const int wt = tid & 63;
    const int r0 = (wt >> 3) << 1;       // rows {r0, r0+1} of 16
    const int b0 = (wt & 7) << 3;        // batches [b0, b0+8)
    const float* w0p = sW + r0*WSTRIDE;
    const float* w1p = w0p + WSTRIDE;
    const int bx = tid >> 2, q = tid & 3;   // x staging assignment

    for (int t = 0; t < TT; ++t){
        const float* hsrc = g_hbuf + (size_t)(t & 1)*HB;

        // async copy of full h (4 chunks of 128 unit-rows) overlapped with compute
#pragma unroll
        for (int c = 0; c < 4; ++c){
#pragma unroll
            for (int i = 0; i < 8; ++i){
                int v = c*2048 + i*NTH + tid;   // float4 index
                cp16(sH_addr + v*16, hsrc + v*4);
            }
            cp_commit();
        }

        // x_t: each thread loads 16 floats of x and stages transposed into sH rows 512..575
        {
            const float* xp = x + ((size_t)bx*TT + t)*64 + q*16;
            float4 xr[4];
#pragma unroll
            for (int i = 0; i < 4; ++i) xr[i] = *reinterpret_cast<const float4*>(xp + i*4);
#pragma unroll
            for (int i = 0; i < 4; ++i){
                int kr = HH + q*16 + i*4;
                sH[(kr  )*BB + bx] = xr[i].x;
                sH[(kr+1)*BB + bx] = xr[i].y;
                sH[(kr+2)*BB + bx] = xr[i].z;
                sH[(kr+3)*BB + bx] = xr[i].w;
            }
        }

        float acc[16];
#pragma unroll
        for (int i = 0; i < 16; ++i) acc[i] = 0.f;

        CP_WAIT(3); __syncthreads();
        GEMM_RANGE(0, 128);
        CP_WAIT(2); __syncthreads();
        GEMM_RANGE(128, 256);
        CP_WAIT(1); __syncthreads();
        GEMM_RANGE(256, 384);
        CP_WAIT(0); __syncthreads();
        GEMM_RANGE(384, 512);
        GEMM_RANGE(512, 576);   // x rows staged before first sync above

        // write k-partials
        {
            float* p0 = sP + (wg*16 + r0)*PSTR + b0;
            float* p1 = sP + (wg*16 + r0 + 1)*PSTR + b0;
            *reinterpret_cast<float4*>(p0    ) = make_float4(acc[0],acc[1],acc[2],acc[3]);
            *reinterpret_cast<float4*>(p0 + 4) = make_float4(acc[4],acc[5],acc[6],acc[7]);
            *reinterpret_cast<float4*>(p1    ) = make_float4(acc[8],acc[9],acc[10],acc[11]);
            *reinterpret_cast<float4*>(p1 + 4) = make_float4(acc[12],acc[13],acc[14],acc[15]);
        }
        __syncthreads();

        // ---- epilogue: 256 threads, one (unit j, batch b) output each
        {
            const int j = tid >> 6, b = tid & 63;
            float gi = 0.f, gf = 0.f, gg = 0.f, go = 0.f;
#pragma unroll
            for (int p = 0; p < 4; ++p){
                gi += sP[(p*16 +      j)*PSTR + b];
                gf += sP[(p*16 +  4 + j)*PSTR + b];
                gg += sP[(p*16 +  8 + j)*PSTR + b];
                go += sP[(p*16 + 12 + j)*PSTR + b];
            }
            gi += sB[j]; gf += sB[4+j]; gg += sB[8+j]; go += sB[12+j];
            float iv = sigf(gi), fv = sigf(gf);
            float gv = tanhf_fast(gg), ov = sigf(go);
            float cold = sC[j*BB + b];
            float hold = sH[(u0+j)*BB + b];
            float cn = fv*cold + iv*gv;
            float hn = ov*tanhf_fast(cn);
            float h2 = 0.5f*(hold + hn);   // K = 0.5 Euler blend
            float c2 = 0.5f*(cold + cn);
            sC[j*BB + b] = c2;
            sO[j*BB + b] = h2;
            g_hbuf[(size_t)((t+1)&1)*HB + (u0+j)*BB + b] = h2;
        }
        __syncthreads();

        // coalesced 16B stores of the step output
        if (tid < BB){
            int b = tid;
            float4 hv4 = make_float4(sO[b], sO[BB+b], sO[2*BB+b], sO[3*BB+b]);
            *reinterpret_cast<float4*>(out_states + ((size_t)b*TT + t)*HH + u0) = hv4;
            if (t == TT-1){
                float4 cv4 = make_float4(sC[b], sC[BB+b], sC[2*BB+b], sC[3*BB+b]);
                *reinterpret_cast<float4*>(out_final + b*(2*HH) + u0) = hv4;
                *reinterpret_cast<float4*>(out_final + b*(2*HH) + HH + u0) = cv4;
            }
        }

        // ---- grid-wide step barrier (all 128 CTAs co-resident; flags monotonic)
        if (t != TT-1){
            if (tid == 0){
                asm volatile("st.release.gpu.global.u32 [%0], %1;\n"
                             :: "l"(&g_flags[blockIdx.x]), "r"((unsigned)(t+1)) : "memory");
            }
            if (tid < GRID){
                unsigned v;
                const int* fp = &g_flags[tid];
                do {
                    asm volatile("ld.acquire.gpu.global.u32 %0, [%1];\n"
                                 : "=r"(v) : "l"(fp) : "memory");
                } while (v < (unsigned)(t+1));
            }
            __syncthreads();
        }
    }
}

extern "C" void kernel_launch(void* const* d_in, const int* in_sizes, int n_in,
                              void* d_out, int out_size)
{
    const float* x    = (const float*)d_in[0];
    const float* W_ih = (const float*)d_in[1];
    const float* W_hh = (const float*)d_in[2];
    const float* b_ih = (const float*)d_in[3];
    const float* b_hh = (const float*)d_in[4];
    float* out        = (float*)d_out;
    float* out_final  = out + (size_t)BB*TT*HH;

    const int smem_bytes = (KTOT*BB + 16*WSTRIDE + 4*16*PSTR + 16 + 4*BB + 4*BB) * 4;
    cudaFuncSetAttribute(stn_kernel, cudaFuncAttributeMaxDynamicSharedMemorySize, smem_bytes);

    stn_init_kernel<<<(2*HB + 127)/128, 128>>>();
    stn_kernel<<<GRID, NTH, smem_bytes>>>(x, W_ih, W_hh, b_ih, b_hh, out, out_final);
}

// round 7
// speedup vs baseline: 2.5738x; 2.5659x over previous
#include <cuda_runtime.h>
#include <cuda_fp16.h>
#include <cstdint>

#define TT 4096
#define BATCH 64
#define HH 512
#define GRID 64
#define NTH 256
#define KH 576          // 512 h + 64 x
#define KSTEPS 36
#define RSH 584         // smem row stride in halves (padded)
#define RSB 1168        // row stride bytes
#define SGS 66          // gate staging stride (floats)

// smem byte offsets
#define OFF_BIAS 0
#define OFF_HI   128            // h2 hi staging [64][8] halves
#define OFF_LO   1152
#define OFF_G    2176           // [32][66] f32 = 8448
#define OFF_A    10624          // [32][584] f16 = 37376
#define OFF_BH   48000          // [64][584] f16 = 74752
#define OFF_BL   122752
#define SMEM_TOTAL 197504

__device__ __align__(16) __half g_hh[2][BATCH*HH];
__device__ __align__(16) __half g_hl[2][BATCH*HH];
__device__ int g_flags[GRID];

__device__ __forceinline__ float sigf(float x){ return 1.f/(1.f+__expf(-x)); }
__device__ __forceinline__ float tanhf_fast(float x){
    float e = __expf(-2.f*fabsf(x));
    return copysignf((1.f-e)/(1.f+e), x);
}
__device__ __forceinline__ unsigned pack2h(float a, float b){
    __half2 h = __floats2half2_rn(a, b);
    return *reinterpret_cast<unsigned*>(&h);
}
__device__ __forceinline__ float lof(float v){ return v - __half2float(__float2half_rn(v)); }

__device__ __forceinline__ void cp16(unsigned dst, const void* src){
    asm volatile("cp.async.cg.shared.global [%0], [%1], 16;\n"::"r"(dst),"l"(src));
}
__device__ __forceinline__ void cp_commit(){ asm volatile("cp.async.commit_group;\n"::); }
#define CP_WAIT(N) asm volatile("cp.async.wait_group %0;\n"::"n"(N))

__device__ __forceinline__ unsigned smem_u32(const void* p){
    unsigned a;
    asm("{ .reg .u64 t; cvta.to.shared.u64 t, %1; cvt.u32.u64 %0, t; }" : "=r"(a) : "l"(p));
    return a;
}

#define LDSM4(r0,r1,r2,r3,addr) \
    asm volatile("ldmatrix.sync.aligned.m8n8.x4.shared.b16 {%0,%1,%2,%3}, [%4];" \
        : "=r"(r0),"=r"(r1),"=r"(r2),"=r"(r3) : "r"(addr))

#define MMA16816(d,a0,a1,a2,a3,b0,b1) \
    asm volatile("mma.sync.aligned.m16n8k16.row.col.f32.f16.f16.f32 " \
        "{%0,%1,%2,%3}, {%4,%5,%6,%7}, {%8,%9}, {%0,%1,%2,%3};" \
        : "+f"((d)[0]),"+f"((d)[1]),"+f"((d)[2]),"+f"((d)[3]) \
        : "r"(a0),"r"(a1),"r"(a2),"r"(a3),"r"(b0),"r"(b1))

__global__ void __launch_bounds__(128,1) stn_init_kernel(){
    int i = blockIdx.x*blockDim.x + threadIdx.x;
    uint4 z = make_uint4(0,0,0,0);
    if (i < 2*BATCH*HH/8){
        reinterpret_cast<uint4*>(g_hh)[i] = z;
        reinterpret_cast<uint4*>(g_hl)[i] = z;
    }
    if (i < GRID) g_flags[i] = 0;
}

__global__ void __launch_bounds__(NTH,1) stn_kernel(
    const float* __restrict__ x,      // [64,4096,64]
    const float* __restrict__ W_ih,   // [2048,64]
    const float* __restrict__ W_hh,   // [2048,512]
    const float* __restrict__ b_ih,
    const float* __restrict__ b_hh,
    float* __restrict__ out_states,   // [64,4096,512]
    float* __restrict__ out_final)    // [64,1024]
{
    extern __shared__ __align__(16) unsigned char smem[];
    float*  sBias = reinterpret_cast<float*>(smem + OFF_BIAS);
    __half* sHI   = reinterpret_cast<__half*>(smem + OFF_HI);
    __half* sLO   = reinterpret_cast<__half*>(smem + OFF_LO);
    float*  sG    = reinterpret_cast<float*>(smem + OFF_G);
    const unsigned S = smem_u32(smem);
    const unsigned sA = S + OFF_A, sBH = S + OFF_BH, sBL = S + OFF_BL;

    const int tid  = threadIdx.x;
    const int lane = tid & 31, warp = tid >> 5;
    const int U0   = blockIdx.x * 8;     // this CTA's 8 hidden units

    // ---- weights: local row r = gate*8 + u  ->  global row gate*512 + U0 + u
    for (int idx = tid; idx < 32*72; idx += NTH){
        int r = idx / 72, c8 = (idx - r*72) * 8;
        int R = (r >> 3)*HH + U0 + (r & 7);
        const float* src = (c8 < HH) ? (W_hh + (size_t)R*HH + c8)
                                     : (W_ih + R*64 + (c8 - HH));
        float4 v0 = *reinterpret_cast<const float4*>(src);
        float4 v1 = *reinterpret_cast<const float4*>(src + 4);
        uint4 pk;
        pk.x = pack2h(v0.x, v0.y); pk.y = pack2h(v0.z, v0.w);
        pk.z = pack2h(v1.x, v1.y); pk.w = pack2h(v1.z, v1.w);
        *reinterpret_cast<uint4*>(smem + OFF_A + r*RSB + c8*2) = pk;
    }
    if (tid < 32){
        int R = (tid >> 3)*HH + U0 + (tid & 7);
        sBias[tid] = b_ih[R] + b_hh[R];
    }
    __syncthreads();

    // ---- mma tiling roles: 2x4 warp grid over M=32, N=64
    const int mrow0 = (warp >> 2) * 16;
    const int nc0   = (warp & 3) * 16;
    const unsigned aAddr  = sA  + (unsigned)(mrow0 + (lane & 15))*RSB + (lane >> 4)*16;
    const unsigned bhAddr = sBH + (unsigned)(nc0   + (lane & 15))*RSB + (lane >> 4)*16;
    const unsigned blAddr = sBL + (unsigned)(nc0   + (lane & 15))*RSB + (lane >> 4)*16;

    const int bx = tid >> 2, q = tid & 3;       // x fill: batch, 16-col group
    const int eu = tid & 7, eb0 = tid >> 3;     // epilogue: unit, batch base (0..31)

    float cr0 = 0.f, cr1 = 0.f, hr0 = 0.f, hr1 = 0.f;   // c,h for (eu,eb0) and (eu,eb0+32)

    for (int t = 0; t < TT; ++t){
        const int par = t & 1, npar = par ^ 1;

        // prefetch x_t (16 floats/thread) before the barrier
        const float* xp = x + ((size_t)bx*TT + t)*64 + q*16;
        float4 xa = *reinterpret_cast<const float4*>(xp);
        float4 xb = *reinterpret_cast<const float4*>(xp + 4);
        float4 xc = *reinterpret_cast<const float4*>(xp + 8);
        float4 xd = *reinterpret_cast<const float4*>(xp + 12);

        // ---- grid-wide step barrier
        if (t){
            if (tid < GRID){
                unsigned v;
                const int* fp = &g_flags[tid];
                do {
                    asm volatile("ld.acquire.gpu.global.u32 %0,[%1];" : "=r"(v) : "l"(fp) : "memory");
                } while (v < (unsigned)t);
            }
            __syncthreads();
        }

        // ---- B fill: h hi then h lo via cp.async (16 chunks each per thread)
        {
            const unsigned char* hsrc = reinterpret_cast<const unsigned char*>(g_hh[par]);
            const unsigned char* lsrc = reinterpret_cast<const unsigned char*>(g_hl[par]);
#pragma unroll
            for (int i = 0; i < 16; ++i){
                int idx = i*NTH + tid;                 // 0..4095
                int b = idx >> 6, ch = idx & 63;
                cp16(sBH + (unsigned)b*RSB + ch*16, hsrc + (size_t)idx*16);
            }
            cp_commit();
#pragma unroll
            for (int i = 0; i < 16; ++i){
                int idx = i*NTH + tid;
                int b = idx >> 6, ch = idx & 63;
                cp16(sBL + (unsigned)b*RSB + ch*16, lsrc + (size_t)idx*16);
            }
            cp_commit();
        }
        // ---- x hi/lo into cols 512..575
        {
            uint4 hi0, hi1, lo0, lo1;
            hi0.x = pack2h(xa.x,xa.y); hi0.y = pack2h(xa.z,xa.w);
            hi0.z = pack2h(xb.x,xb.y); hi0.w = pack2h(xb.z,xb.w);
            hi1.x = pack2h(xc.x,xc.y); hi1.y = pack2h(xc.z,xc.w);
            hi1.z = pack2h(xd.x,xd.y); hi1.w = pack2h(xd.z,xd.w);
            lo0.x = pack2h(lof(xa.x),lof(xa.y)); lo0.y = pack2h(lof(xa.z),lof(xa.w));
            lo0.z = pack2h(lof(xb.x),lof(xb.y)); lo0.w = pack2h(lof(xb.z),lof(xb.w));
            lo1.x = pack2h(lof(xc.x),lof(xc.y)); lo1.y = pack2h(lof(xc.z),lof(xc.w));
            lo1.z = pack2h(lof(xd.x),lof(xd.y)); lo1.w = pack2h(lof(xd.z),lof(xd.w));
            unsigned off = (unsigned)bx*RSB + 1024 + q*32;
            *reinterpret_cast<uint4*>(smem + OFF_BH + off)      = hi0;
            *reinterpret_cast<uint4*>(smem + OFF_BH + off + 16) = hi1;
            *reinterpret_cast<uint4*>(smem + OFF_BL + off)      = lo0;
            *reinterpret_cast<uint4*>(smem + OFF_BL + off + 16) = lo1;
        }

        float d0[4] = {0.f,0.f,0.f,0.f};
        float d1[4] = {0.f,0.f,0.f,0.f};

        CP_WAIT(1);            // hi image complete (this thread)
        __syncthreads();       // all threads' hi chunks + x visible

        // ---- pass 1: W * s_hi   (lo image still copying)
#pragma unroll
        for (int ks = 0; ks < KSTEPS; ++ks){
            unsigned a0,a1,a2,a3,b0,b1,b2,b3;
            LDSM4(a0,a1,a2,a3, aAddr  + ks*32);
            LDSM4(b0,b1,b2,b3, bhAddr + ks*32);
            MMA16816(d0, a0,a1,a2,a3, b0,b2);
            MMA16816(d1, a0,a1,a2,a3, b1,b3);
        }
        CP_WAIT(0);
        __syncthreads();
        // ---- pass 2: + W * s_lo
#pragma unroll
        for (int ks = 0; ks < KSTEPS; ++ks){
            unsigned a0,a1,a2,a3,b0,b1,b2,b3;
            LDSM4(a0,a1,a2,a3, aAddr  + ks*32);
            LDSM4(b0,b1,b2,b3, blAddr + ks*32);
            MMA16816(d0, a0,a1,a2,a3, b0,b2);
            MMA16816(d1, a0,a1,a2,a3, b1,b3);
        }

        // ---- fragments -> gate staging
        {
            int r = mrow0 + (lane >> 2), c = nc0 + (lane & 3)*2;
            *reinterpret_cast<float2*>(sG + (r    )*SGS + c    ) = make_float2(d0[0], d0[1]);
            *reinterpret_cast<float2*>(sG + (r + 8)*SGS + c    ) = make_float2(d0[2], d0[3]);
            *reinterpret_cast<float2*>(sG + (r    )*SGS + c + 8) = make_float2(d1[0], d1[1]);
            *reinterpret_cast<float2*>(sG + (r + 8)*SGS + c + 8) = make_float2(d1[2], d1[3]);
        }
        __syncthreads();

        // ---- epilogue: 2 cells per thread: (eu, eb0) and (eu, eb0+32)
#pragma unroll
        for (int half = 0; half < 2; ++half){
            int b = eb0 + half*32;
            float gi = sG[(     eu)*SGS + b] + sBias[eu];
            float gf = sG[( 8 + eu)*SGS + b] + sBias[ 8 + eu];
            float gg = sG[(16 + eu)*SGS + b] + sBias[16 + eu];
            float go = sG[(24 + eu)*SGS + b] + sBias[24 + eu];
            float iv = sigf(gi), fv = sigf(gf);
            float gv = tanhf_fast(gg), ov = sigf(go);
            float cold = half ? cr1 : cr0;
            float hold = half ? hr1 : hr0;
            float cn = fv*cold + iv*gv;
            float hn = ov*tanhf_fast(cn);
            float h2 = 0.5f*(hold + hn);     // K = 0.5 Euler blend
            float c2 = 0.5f*(cold + cn);
            if (half){ cr1 = c2; hr1 = h2; } else { cr0 = c2; hr0 = h2; }
            __half hh = __float2half_rn(h2);
            sHI[b*8 + eu] = hh;
            sLO[b*8 + eu] = __float2half_rn(h2 - __half2float(hh));
            out_states[((size_t)b*TT + t)*HH + U0 + eu] = h2;
            if (t == TT-1){
                out_final[(size_t)b*1024 +       U0 + eu] = h2;
                out_final[(size_t)b*1024 + 512 + U0 + eu] = c2;
            }
        }
        __syncthreads();

        // ---- publish next h images (16B per batch row)
        if (tid < BATCH){
            uint4 vh = *reinterpret_cast<uint4*>(sHI + tid*8);
            uint4 vl = *reinterpret_cast<uint4*>(sLO + tid*8);
            *reinterpret_cast<uint4*>(g_hh[npar] + tid*HH + U0) = vh;
            *reinterpret_cast<uint4*>(g_hl[npar] + tid*HH + U0) = vl;
        }

        if (t != TT-1){
            __syncthreads();
            if (tid == 0){
                asm volatile("st.release.gpu.global.u32 [%0], %1;"
                             :: "l"(&g_flags[blockIdx.x]), "r"((unsigned)(t+1)) : "memory");
            }
        }
    }
}

extern "C" void kernel_launch(void* const* d_in, const int* in_sizes, int n_in,
                              void* d_out, int out_size)
{
    const float* x    = (const float*)d_in[0];
    const float* W_ih = (const float*)d_in[1];
    const float* W_hh = (const float*)d_in[2];
    const float* b_ih = (const float*)d_in[3];
    const float* b_hh = (const float*)d_in[4];
    float* out        = (float*)d_out;
    float* out_final  = out + (size_t)BATCH*TT*HH;

    cudaFuncSetAttribute(stn_kernel, cudaFuncAttributeMaxDynamicSharedMemorySize, SMEM_TOTAL);
    stn_init_kernel<<<64, 128>>>();
    stn_kernel<<<GRID, NTH, SMEM_TOTAL>>>(x, W_ih, W_hh, b_ih, b_hh, out, out_final);
}

// round 10
// speedup vs baseline: 3.5439x; 1.3769x over previous
#include <cuda_runtime.h>
#include <cuda_fp16.h>
#include <cstdint>

#define TT 4096
#define BATCH 64
#define HH 512
#define GRID 64
#define NTH 256
#define KSTEPS 36
#define RSB 1168        // B/A row stride bytes (584 halves, padded)
#define SGS 66          // gate staging stride (floats)

// smem byte offsets
#define OFF_BIAS 0              // 32 f32
#define OFF_HI   128            // h2 staging [64][8] halves = 1024B
#define OFF_OUT  1152           // h2 f32 staging [64][8] = 2048B
#define OFF_G    3200           // [32][66] f32 = 8448
#define OFF_A    11648          // [32][584] f16 = 37376
#define OFF_BH   49024          // [64][584] f16 = 74752
#define SMEM_TOTAL 123776

__device__ __align__(16) __half g_hh[2][BATCH*HH];
__device__ int g_flags[GRID];

__device__ __forceinline__ float sigf(float x){ return 1.f/(1.f+__expf(-x)); }
__device__ __forceinline__ float tanhf_fast(float x){
    float e = __expf(-2.f*fabsf(x));
    return copysignf((1.f-e)/(1.f+e), x);
}
__device__ __forceinline__ unsigned pack2h(float a, float b){
    __half2 h = __floats2half2_rn(a, b);
    return *reinterpret_cast<unsigned*>(&h);
}
__device__ __forceinline__ void cp16(unsigned dst, const void* src){
    asm volatile("cp.async.cg.shared.global [%0], [%1], 16;\n"::"r"(dst),"l"(src));
}
__device__ __forceinline__ void cp_commit(){ asm volatile("cp.async.commit_group;\n"::); }
#define CP_WAIT(N) asm volatile("cp.async.wait_group %0;\n"::"n"(N))

__device__ __forceinline__ unsigned smem_u32(const void* p){
    unsigned a;
    asm("{ .reg .u64 t; cvta.to.shared.u64 t, %1; cvt.u32.u64 %0, t; }" : "=r"(a) : "l"(p));
    return a;
}

#define LDSM4(r0,r1,r2,r3,addr) \
    asm volatile("ldmatrix.sync.aligned.m8n8.x4.shared.b16 {%0,%1,%2,%3}, [%4];" \
        : "=r"(r0),"=r"(r1),"=r"(r2),"=r"(r3) : "r"(addr))

#define MMA16816(d,a0,a1,a2,a3,b0,b1) \
    asm volatile("mma.sync.aligned.m16n8k16.row.col.f32.f16.f16.f32 " \
        "{%0,%1,%2,%3}, {%4,%5,%6,%7}, {%8,%9}, {%0,%1,%2,%3};" \
        : "+f"((d)[0]),"+f"((d)[1]),"+f"((d)[2]),"+f"((d)[3]) \
        : "r"(a0),"r"(a1),"r"(a2),"r"(a3),"r"(b0),"r"(b1))

__global__ void __launch_bounds__(128,1) stn_init_kernel(){
    int i = blockIdx.x*blockDim.x + threadIdx.x;
    if (i < 2*BATCH*HH/8)
        reinterpret_cast<uint4*>(g_hh)[i] = make_uint4(0,0,0,0);
    if (i < GRID) g_flags[i] = 0;
}

__global__ void __launch_bounds__(NTH,1) stn_kernel(
    const float* __restrict__ x,      // [64,4096,64]
    const float* __restrict__ W_ih,   // [2048,64]
    const float* __restrict__ W_hh,   // [2048,512]
    const float* __restrict__ b_ih,
    const float* __restrict__ b_hh,
    float* __restrict__ out_states,   // [64,4096,512]
    float* __restrict__ out_final)    // [64,1024]
{
    extern __shared__ __align__(16) unsigned char smem[];
    float*  sBias = reinterpret_cast<float*>(smem + OFF_BIAS);
    __half* sHI   = reinterpret_cast<__half*>(smem + OFF_HI);
    float*  sOUT  = reinterpret_cast<float*>(smem + OFF_OUT);
    float*  sG    = reinterpret_cast<float*>(smem + OFF_G);
    const unsigned S = smem_u32(smem);
    const unsigned sA = S + OFF_A, sBH = S + OFF_BH;

    const int tid  = threadIdx.x;
    const int lane = tid & 31, warp = tid >> 5;
    const int U0   = blockIdx.x * 8;     // this CTA's 8 hidden units

    // ---- weights: local row r = gate*8 + u  ->  global row gate*512 + U0 + u
    for (int idx = tid; idx < 32*72; idx += NTH){
        int r = idx / 72, c8 = (idx - r*72) * 8;
        int R = (r >> 3)*HH + U0 + (r & 7);
        const float* src = (c8 < HH) ? (W_hh + (size_t)R*HH + c8)
                                     : (W_ih + R*64 + (c8 - HH));
        float4 v0 = *reinterpret_cast<const float4*>(src);
        float4 v1 = *reinterpret_cast<const float4*>(src + 4);
        uint4 pk;
        pk.x = pack2h(v0.x, v0.y); pk.y = pack2h(v0.z, v0.w);
        pk.z = pack2h(v1.x, v1.y); pk.w = pack2h(v1.z, v1.w);
        *reinterpret_cast<uint4*>(smem + OFF_A + r*RSB + c8*2) = pk;
    }
    if (tid < 32){
        int R = (tid >> 3)*HH + U0 + (tid & 7);
        sBias[tid] = b_ih[R] + b_hh[R];
    }
    __syncthreads();

    // ---- mma tiling roles: 2x4 warp grid over M=32, N=64
    const int mrow0 = (warp >> 2) * 16;
    const int nc0   = (warp & 3) * 16;
    const unsigned aAddr  = sA  + (unsigned)(mrow0 + (lane & 15))*RSB + (lane >> 4)*16;
    const unsigned bhAddr = sBH + (unsigned)(nc0   + (lane & 15))*RSB + (lane >> 4)*16;

    const int bx = tid >> 2, q = tid & 3;       // x fill: batch, 16-col group
    const int eu = tid & 7, eb0 = tid >> 3;     // epilogue: unit, batch base (0..31)

    float cr0 = 0.f, cr1 = 0.f, hr0 = 0.f, hr1 = 0.f;

    for (int t = 0; t < TT; ++t){
        const int par = t & 1, npar = par ^ 1;

        // prefetch x_t (16 floats/thread) before the barrier
        const float* xp = x + ((size_t)bx*TT + t)*64 + q*16;
        float4 xa = *reinterpret_cast<const float4*>(xp);
        float4 xb = *reinterpret_cast<const float4*>(xp + 4);
        float4 xc = *reinterpret_cast<const float4*>(xp + 8);
        float4 xd = *reinterpret_cast<const float4*>(xp + 12);

        // ---- grid-wide step barrier
        if (t){
            if (tid < GRID){
                unsigned v;
                const int* fp = &g_flags[tid];
                do {
                    asm volatile("ld.acquire.gpu.global.u32 %0,[%1];" : "=r"(v) : "l"(fp) : "memory");
                } while (v < (unsigned)t);
            }
            __syncthreads();
        }

        // ---- B fill: h image in 2 K-column chunks (pipelined with MMA)
        {
            const unsigned char* hsrc = reinterpret_cast<const unsigned char*>(g_hh[par]);
#pragma unroll
            for (int i = 0; i < 8; ++i){             // chunk 0: cols 0..255
                int idx = i*NTH + tid;               // 0..2047
                int b = idx >> 5, ch = idx & 31;
                cp16(sBH + (unsigned)b*RSB + ch*16, hsrc + (size_t)b*1024 + ch*16);
            }
            cp_commit();
#pragma unroll
            for (int i = 0; i < 8; ++i){             // chunk 1: cols 256..511
                int idx = i*NTH + tid;
                int b = idx >> 5, ch = idx & 31;
                cp16(sBH + (unsigned)b*RSB + 512 + ch*16, hsrc + (size_t)b*1024 + 512 + ch*16);
            }
            cp_commit();
        }
        // ---- x into cols 512..575 (plain STS, visible after first sync)
        {
            uint4 hi0, hi1;
            hi0.x = pack2h(xa.x,xa.y); hi0.y = pack2h(xa.z,xa.w);
            hi0.z = pack2h(xb.x,xb.y); hi0.w = pack2h(xb.z,xb.w);
            hi1.x = pack2h(xc.x,xc.y); hi1.y = pack2h(xc.z,xc.w);
            hi1.z = pack2h(xd.x,xd.y); hi1.w = pack2h(xd.z,xd.w);
            unsigned off = (unsigned)bx*RSB + 1024 + q*32;
            *reinterpret_cast<uint4*>(smem + OFF_BH + off)      = hi0;
            *reinterpret_cast<uint4*>(smem + OFF_BH + off + 16) = hi1;
        }

        float d0[4] = {0.f,0.f,0.f,0.f};
        float d1[4] = {0.f,0.f,0.f,0.f};

        CP_WAIT(1);            // chunk 0 landed (this thread)
        __syncthreads();       // all threads' chunk-0 + x visible

#pragma unroll
        for (int ks = 0; ks < 16; ++ks){
            unsigned a0,a1,a2,a3,b0,b1,b2,b3;
            LDSM4(a0,a1,a2,a3, aAddr  + ks*32);
            LDSM4(b0,b1,b2,b3, bhAddr + ks*32);
            MMA16816(d0, a0,a1,a2,a3, b0,b2);
            MMA16816(d1, a0,a1,a2,a3, b1,b3);
        }
        CP_WAIT(0);
        __syncthreads();
#pragma unroll
        for (int ks = 16; ks < KSTEPS; ++ks){
            unsigned a0,a1,a2,a3,b0,b1,b2,b3;
            LDSM4(a0,a1,a2,a3, aAddr  + ks*32);
            LDSM4(b0,b1,b2,b3, bhAddr + ks*32);
            MMA16816(d0, a0,a1,a2,a3, b0,b2);
            MMA16816(d1, a0,a1,a2,a3, b1,b3);
        }

        // ---- fragments -> gate staging
        {
            int r = mrow0 + (lane >> 2), c = nc0 + (lane & 3)*2;
            *reinterpret_cast<float2*>(sG + (r    )*SGS + c    ) = make_float2(d0[0], d0[1]);
            *reinterpret_cast<float2*>(sG + (r + 8)*SGS + c    ) = make_float2(d0[2], d0[3]);
            *reinterpret_cast<float2*>(sG + (r    )*SGS + c + 8) = make_float2(d1[0], d1[1]);
            *reinterpret_cast<float2*>(sG + (r + 8)*SGS + c + 8) = make_float2(d1[2], d1[3]);
        }
        __syncthreads();

        // ---- epilogue: 2 cells per thread: (eu, eb0) and (eu, eb0+32)
#pragma unroll
        for (int half = 0; half < 2; ++half){
            int b = eb0 + half*32;
            float gi = sG[(     eu)*SGS + b] + sBias[eu];
            float gf = sG[( 8 + eu)*SGS + b] + sBias[ 8 + eu];
            float gg = sG[(16 + eu)*SGS + b] + sBias[16 + eu];
            float go = sG[(24 + eu)*SGS + b] + sBias[24 + eu];
            float iv = sigf(gi), fv = sigf(gf);
            float gv = tanhf_fast(gg), ov = sigf(go);
            float cold = half ? cr1 : cr0;
            float hold = half ? hr1 : hr0;
            float cn = fv*cold + iv*gv;
            float hn = ov*tanhf_fast(cn);
            float h2 = 0.5f*(hold + hn);     // K = 0.5 Euler blend
            float c2 = 0.5f*(cold + cn);
            if (half){ cr1 = c2; hr1 = h2; } else { cr0 = c2; hr0 = h2; }
            sHI[b*8 + eu]  = __float2half_rn(h2);
            sOUT[b*8 + eu] = h2;
            if (t == TT-1){
                out_final[(size_t)b*1024 +       U0 + eu] = h2;
                out_final[(size_t)b*1024 + 512 + U0 + eu] = c2;
            }
        }
        __syncthreads();

        // ---- publish next h image (16B per batch row), then release the flag
        if (tid < BATCH){
            uint4 vh = *reinterpret_cast<uint4*>(sHI + tid*8);
            *reinterpret_cast<uint4*>(g_hh[npar] + tid*HH + U0) = vh;
        }
        __syncthreads();
        if (t != TT-1 && tid == 0){
            asm volatile("st.release.gpu.global.u32 [%0], %1;"
                         :: "l"(&g_flags[blockIdx.x]), "r"((unsigned)(t+1)) : "memory");
        }

        // ---- step output stores: OFF the critical path (after flag release)
        if (tid < BATCH){
            float4 v0 = *reinterpret_cast<float4*>(sOUT + tid*8);
            float4 v1 = *reinterpret_cast<float4*>(sOUT + tid*8 + 4);
            float* dst = out_states + ((size_t)tid*TT + t)*HH + U0;
            *reinterpret_cast<float4*>(dst)     = v0;
            *reinterpret_cast<float4*>(dst + 4) = v1;
        }
    }
}

extern "C" void kernel_launch(void* const* d_in, const int* in_sizes, int n_in,
                              void* d_out, int out_size)
{
    const float* x    = (const float*)d_in[0];
    const float* W_ih = (const float*)d_in[1];
    const float* W_hh = (const float*)d_in[2];
    const float* b_ih = (const float*)d_in[3];
    const float* b_hh = (const float*)d_in[4];
    float* out        = (float*)d_out;
    float* out_final  = out + (size_t)BATCH*TT*HH;

    cudaFuncSetAttribute(stn_kernel, cudaFuncAttributeMaxDynamicSharedMemorySize, SMEM_TOTAL);
    stn_init_kernel<<<64, 128>>>();
    stn_kernel<<<GRID, NTH, SMEM_TOTAL>>>(x, W_ih, W_hh, b_ih, b_hh, out, out_final);
}